// round 10
// baseline (speedup 1.0000x reference)
#include <cuda_runtime.h>
#include <cuda_bf16.h>
#include <cstdint>

#define NNODE 32768
#define LSEQ  2048

// ---------------- device scratch (no allocation allowed) -------------------
__device__ __align__(16) __nv_bfloat16 g_A1 [NNODE * 256];   // [N, 2*128]  X hi|lo
__device__ __align__(16) __nv_bfloat16 g_A2 [NNODE * 512];   // [N, 2*256]  H1 hi|lo
__device__ __align__(16) __nv_bfloat16 g_A3 [NNODE * 512];   // [N, 2*256]  H2 hi|lo
__device__ __align__(16) __nv_bfloat16 g_SA [NNODE * 128];   // [N, 128]  S.X
__device__ __align__(16) __nv_bfloat16 g_SH [NNODE * 256];   // [N, 256]  S.H1
__device__ __align__(16) __nv_bfloat16 g_B1s[256 * 512];     // [Wrel1h|Wroot1h|Wroot1l|Wroot1h]
__device__ __align__(16) __nv_bfloat16 g_B2s[256 * 1024];    // same, K=256
__device__ __align__(16) __nv_bfloat16 g_Bfs[128 * 768];     // [Wfch|Wfcl|Wfch]

// ---------------- PTX helpers ----------------------------------------------
static __device__ __forceinline__ void cp16(uint32_t dst, const void* src) {
    asm volatile("cp.async.cg.shared.global [%0], [%1], 16;" :: "r"(dst), "l"(src) : "memory");
}
static __device__ __forceinline__ void cp_commit() {
    asm volatile("cp.async.commit_group;" ::: "memory");
}

#define LDSM4(r0, r1, r2, r3, a) \
    asm volatile("ldmatrix.sync.aligned.m8n8.x4.shared.b16 {%0,%1,%2,%3}, [%4];" \
                 : "=r"(r0), "=r"(r1), "=r"(r2), "=r"(r3) : "r"(a))

#define MMA16816(d, a, b0, b1) \
    asm volatile("mma.sync.aligned.m16n8k16.row.col.f32.bf16.bf16.f32 " \
                 "{%0,%1,%2,%3}, {%4,%5,%6,%7}, {%8,%9}, {%0,%1,%2,%3};" \
                 : "+f"((d)[0]), "+f"((d)[1]), "+f"((d)[2]), "+f"((d)[3]) \
                 : "r"((a)[0]), "r"((a)[1]), "r"((a)[2]), "r"((a)[3]), \
                   "r"(b0), "r"(b1))

static __device__ __forceinline__ uint32_t pack_bf16(float x, float y) {
    __nv_bfloat16 h0 = __float2bfloat16_rn(x), h1 = __float2bfloat16_rn(y);
    return ((uint32_t)__bfloat16_as_ushort(h1) << 16) | __bfloat16_as_ushort(h0);
}

// ---------------------------------------------------------------------------
// Segmented-K bf16 HMMA GEMM, virtual K = NSEG*KK, BK=32, 4-stage cp.async
// pipeline + register double-buffered mainloop, MMA-before-wait overlap.
// CTA tile 256x128, 8 warps (4M x 2N), warp tile 64x64. 1 CTA/SM.
// Smem rows: 32 bf16 = 64B data at 80B stride (16B-aligned; ldmatrix phases
// conflict-free, cp.async stores 2-way max on the async path).
// ---------------------------------------------------------------------------
#define ROWB   80
#define ATILE  (256 * ROWB)          // 20480
#define BTILE  (128 * ROWB)          // 10240
#define STAGEB (ATILE + BTILE)       // 30720
#define NSTG   4

struct Frag { uint32_t a[4][4]; uint32_t b[4][4]; };

template <int NSEG, bool LAYER>
__global__ __launch_bounds__(256, 1)
void gemm_mma(const __nv_bfloat16* __restrict__ A0, const __nv_bfloat16* __restrict__ A1p,
              const __nv_bfloat16* __restrict__ A2p, const __nv_bfloat16* __restrict__ A3p,
              int l0, int l1, int l2, int l3,
              const __nv_bfloat16* __restrict__ Bs,
              const float* __restrict__ bias, const float* __restrict__ slope,
              void* __restrict__ OutP, int KK, int ldout)
{
    extern __shared__ __align__(16) char smem[];   // NSTG * STAGEB = 122880
    const uint32_t sb = (uint32_t)__cvta_generic_to_shared(smem);

    const int tid    = threadIdx.x;
    const int lane   = tid & 31;
    const int wid    = tid >> 5;
    const int warp_m = wid & 3;          // 0..3 -> 64-row block
    const int warp_n = wid >> 2;         // 0..1 -> 64-col block
    const int bm     = blockIdx.y * 256;
    const int bn     = blockIdx.x * 128;
    const int ldb    = NSEG * KK;
    const int nkk    = KK >> 5;
    const int nc     = NSEG * nkk;

    // per-thread load geometry: 4 16B units for A (256 rows), 2 for B (128 rows)
    int rA[4], qA[4];
    const __nv_bfloat16* bsrc[2]; uint32_t adst[4], bdst[2];
#pragma unroll
    for (int i = 0; i < 4; ++i) {
        int u = i * 256 + tid, r = u >> 2, q = u & 3;
        rA[i] = r; qA[i] = q;
        adst[i] = sb + (uint32_t)(r * ROWB + q * 16);
    }
#pragma unroll
    for (int i = 0; i < 2; ++i) {
        int u = i * 256 + tid, r = u >> 2, q = u & 3;
        bsrc[i] = Bs + (size_t)(bn + r) * ldb + q * 8;
        bdst[i] = sb + ATILE + (uint32_t)(r * ROWB + q * 16);
    }

    auto issue = [&](int c) {
        if (c < nc) {
            int seg;
            if (NSEG == 4) seg = (c >= 3 * nkk) ? 3 : (c >= 2 * nkk) ? 2 : (c >= nkk) ? 1 : 0;
            else           seg = (c >= 2 * nkk) ? 2 : (c >= nkk) ? 1 : 0;
            const __nv_bfloat16* ab; int al;
            if      (seg == 0) { ab = A0;  al = l0; }
            else if (seg == 1) { ab = A1p; al = l1; }
            else if (seg == 2) { ab = A2p; al = l2; }
            else               { ab = A3p; al = l3; }
            const __nv_bfloat16* arow = ab + (size_t)bm * al + (c - seg * nkk) * 32;
            uint32_t st = (uint32_t)(c & (NSTG - 1)) * STAGEB;
#pragma unroll
            for (int i = 0; i < 4; ++i) cp16(adst[i] + st, arow + (size_t)rA[i] * al + qA[i] * 8);
#pragma unroll
            for (int i = 0; i < 2; ++i) cp16(bdst[i] + st, bsrc[i] + c * 32);
        }
        cp_commit();   // dummy groups keep wait_group counting valid
    };

    // ldmatrix addresses (stage/k-step invariant)
    uint32_t aAddr[4];
#pragma unroll
    for (int m = 0; m < 4; ++m) {
        int row = warp_m * 64 + m * 16 + (lane & 15);
        aAddr[m] = sb + (uint32_t)(row * ROWB + (lane >> 4) * 16);
    }
    uint32_t bAddr[4];
#pragma unroll
    for (int p = 0; p < 4; ++p) {
        int row = warp_n * 64 + (2 * p + (lane >> 4)) * 8 + (lane & 7);
        bAddr[p] = sb + ATILE + (uint32_t)(row * ROWB + ((lane >> 3) & 1) * 16);
    }

    auto ldsm_frag = [&](Frag& f, uint32_t off) {
#pragma unroll
        for (int m = 0; m < 4; ++m)
            LDSM4(f.a[m][0], f.a[m][1], f.a[m][2], f.a[m][3], aAddr[m] + off);
#pragma unroll
        for (int p = 0; p < 4; ++p)
            LDSM4(f.b[p][0], f.b[p][1], f.b[p][2], f.b[p][3], bAddr[p] + off);
    };

    float acc[4][8][4];
#pragma unroll
    for (int m = 0; m < 4; ++m)
#pragma unroll
        for (int n = 0; n < 8; ++n)
#pragma unroll
            for (int j = 0; j < 4; ++j) acc[m][n][j] = 0.0f;

    auto mma_frag = [&](const Frag& f) {
#pragma unroll
        for (int m = 0; m < 4; ++m)
#pragma unroll
            for (int n = 0; n < 8; ++n)
                MMA16816(acc[m][n], f.a[m], f.b[n >> 1][(n & 1) * 2], f.b[n >> 1][(n & 1) * 2 + 1]);
    };

    // prologue: stages 0..2 in flight, chunk 0 resident, frag0 primed
    issue(0); issue(1); issue(2);
    asm volatile("cp.async.wait_group 2;" ::: "memory");
    __syncthreads();

    Frag f0, f1;
    ldsm_frag(f0, 0);                       // chunk 0, ks 0

    for (int s = 0; s < nc; ++s) {
        const uint32_t st = (uint32_t)(s & (NSTG - 1)) * STAGEB;

        // ks0: prime ks1 frags, refill pipeline, MMA ks0
        ldsm_frag(f1, st + 32);
        issue(s + 3);
        mma_frag(f0);

        // ks1: MMA first (drains on tensor pipe under the wait/barrier),
        // then advance smem pipeline and prime next chunk's ks0.
        mma_frag(f1);
        asm volatile("cp.async.wait_group 2;" ::: "memory");   // chunk s+1 resident
        __syncthreads();                                        // all warps done reading stage s
        ldsm_frag(f0, (uint32_t)((s + 1) & (NSTG - 1)) * STAGEB);  // junk on last iter, in-bounds
    }

    // ---- epilogue ----------------------------------------------------------
    if (LAYER) {
        __nv_bfloat16* Aout = (__nv_bfloat16*)OutP;
        const int KKout = ldout >> 1;
        const float a = __ldg(slope);
#pragma unroll
        for (int m = 0; m < 4; ++m) {
            const int r0 = bm + warp_m * 64 + m * 16 + (lane >> 2);
#pragma unroll
            for (int n = 0; n < 8; ++n) {
                const int c0 = bn + warp_n * 64 + n * 8 + (lane & 3) * 2;
                const float bx = __ldg(&bias[c0]), by = __ldg(&bias[c0 + 1]);
#pragma unroll
                for (int h = 0; h < 2; ++h) {
                    float vx = acc[m][n][h * 2 + 0] + bx;
                    float vy = acc[m][n][h * 2 + 1] + by;
                    vx = vx >= 0.f ? vx : a * vx;
                    vy = vy >= 0.f ? vy : a * vy;
                    __nv_bfloat16 hx = __float2bfloat16_rn(vx), hy = __float2bfloat16_rn(vy);
                    float rx = vx - __bfloat162float(hx), ry = vy - __bfloat162float(hy);
                    uint32_t hi = ((uint32_t)__bfloat16_as_ushort(hy) << 16) | __bfloat16_as_ushort(hx);
                    uint32_t lo = pack_bf16(rx, ry);
                    const size_t base = (size_t)(r0 + h * 8) * ldout + c0;
                    *(uint32_t*)&Aout[base]         = hi;
                    *(uint32_t*)&Aout[base + KKout] = lo;
                }
            }
        }
    } else {
        float* C = (float*)OutP;
#pragma unroll
        for (int m = 0; m < 4; ++m) {
            const int r0 = bm + warp_m * 64 + m * 16 + (lane >> 2);
#pragma unroll
            for (int n = 0; n < 8; ++n) {
                const int c0 = bn + warp_n * 64 + n * 8 + (lane & 3) * 2;
                const float bx = __ldg(&bias[c0]), by = __ldg(&bias[c0 + 1]);
                *(float2*)(C + (size_t)r0 * ldout + c0) =
                    make_float2(acc[m][n][0] + bx, acc[m][n][1] + by);
                *(float2*)(C + (size_t)(r0 + 8) * ldout + c0) =
                    make_float2(acc[m][n][2] + bx, acc[m][n][3] + by);
            }
        }
    }
}

// ---------------------------------------------------------------------------
// Fused prep: all weight hi/lo stacks + X hi/lo split + S.X  (one launch)
// ---------------------------------------------------------------------------
static __device__ __forceinline__ void split_unit(
    const float* __restrict__ src, __nv_bfloat16* __restrict__ dst,
    int ldb, int offH, int offL, int offH2, int K, int idx)
{
    const int per = K >> 2;
    const int row = idx / per;
    const int j   = (idx - row * per) << 2;
    float4 v = *(const float4*)(src + (size_t)row * K + j);
    __nv_bfloat16 h0 = __float2bfloat16_rn(v.x), h1 = __float2bfloat16_rn(v.y);
    __nv_bfloat16 h2 = __float2bfloat16_rn(v.z), h3 = __float2bfloat16_rn(v.w);
    uint2 hh;
    hh.x = ((uint32_t)__bfloat16_as_ushort(h1) << 16) | __bfloat16_as_ushort(h0);
    hh.y = ((uint32_t)__bfloat16_as_ushort(h3) << 16) | __bfloat16_as_ushort(h2);
    *(uint2*)(dst + (size_t)row * ldb + offH + j) = hh;
    if (offL >= 0) {
        uint2 ll;
        ll.x = pack_bf16(v.x - __bfloat162float(h0), v.y - __bfloat162float(h1));
        ll.y = pack_bf16(v.z - __bfloat162float(h2), v.w - __bfloat162float(h3));
        *(uint2*)(dst + (size_t)row * ldb + offL + j) = ll;
    }
    if (offH2 >= 0)
        *(uint2*)(dst + (size_t)row * ldb + offH2 + j) = hh;
}

__global__ void prep_all(const float* __restrict__ X, const float* __restrict__ ea,
                         const float* __restrict__ W_rel1, const float* __restrict__ W_root1,
                         const float* __restrict__ W_rel2, const float* __restrict__ W_root2,
                         const float* __restrict__ W_fc,
                         __nv_bfloat16* __restrict__ B1s, __nv_bfloat16* __restrict__ B2s,
                         __nv_bfloat16* __restrict__ Bfs,
                         __nv_bfloat16* __restrict__ A1, __nv_bfloat16* __restrict__ SA)
{
    const int b   = blockIdx.x;
    const int tid = threadIdx.x;

    if (b < 224) {   // weight prep
        if (b < 32)       split_unit(W_rel1,  B1s,  512,   0,  -1,  -1, 128, b * 256 + tid);
        else if (b < 64)  split_unit(W_root1, B1s,  512, 128, 256, 384, 128, (b - 32) * 256 + tid);
        else if (b < 128) split_unit(W_rel2,  B2s, 1024,   0,  -1,  -1, 256, (b - 64) * 256 + tid);
        else if (b < 192) split_unit(W_root2, B2s, 1024, 256, 512, 768, 256, (b - 128) * 256 + tid);
        else              split_unit(W_fc,    Bfs,  768,   0, 256, 512, 256, (b - 192) * 256 + tid);
        return;
    }

    // X prep: hi/lo split + window shift
    const int idx = (b - 224) * 256 + tid;      // 0 .. N*32
    const int row = idx >> 5;
    const int col = (idx & 31) << 2;
    const int t   = row & (LSEQ - 1);

    float4 v = *(const float4*)(X + (size_t)row * 128 + col);
    __nv_bfloat16 h0 = __float2bfloat16_rn(v.x), h1 = __float2bfloat16_rn(v.y);
    __nv_bfloat16 h2 = __float2bfloat16_rn(v.z), h3 = __float2bfloat16_rn(v.w);
    uint2 hh, ll;
    hh.x = ((uint32_t)__bfloat16_as_ushort(h1) << 16) | __bfloat16_as_ushort(h0);
    hh.y = ((uint32_t)__bfloat16_as_ushort(h3) << 16) | __bfloat16_as_ushort(h2);
    ll.x = pack_bf16(v.x - __bfloat162float(h0), v.y - __bfloat162float(h1));
    ll.y = pack_bf16(v.z - __bfloat162float(h2), v.w - __bfloat162float(h3));
    *(uint2*)(A1 + (size_t)row * 256 + col)       = hh;
    *(uint2*)(A1 + (size_t)row * 256 + 128 + col) = ll;

    const int starts[8] = {0, 2047, 4093, 6138, 8182, 10225, 12267, 14308};
    float4 s = make_float4(0.f, 0.f, 0.f, 0.f);
#pragma unroll
    for (int d = 1; d <= 8; ++d) {
        if (t >= d) {
            const float wd = __ldg(&ea[starts[d - 1]]);
            float4 xd = *(const float4*)(X + (size_t)(row - d) * 128 + col);
            s.x = fmaf(wd, xd.x, s.x); s.y = fmaf(wd, xd.y, s.y);
            s.z = fmaf(wd, xd.z, s.z); s.w = fmaf(wd, xd.w, s.w);
        }
    }
    uint2 so;
    so.x = pack_bf16(s.x, s.y);
    so.y = pack_bf16(s.z, s.w);
    *(uint2*)(SA + (size_t)row * 128 + col) = so;
}

// ---------------------------------------------------------------------------
// shift_h: SH[i,:] = sum_d w_d * Hh[i-d,:]   (Hh = hi half of [N, 512] layout)
// ---------------------------------------------------------------------------
__global__ void shift_h(const __nv_bfloat16* __restrict__ Hh, const float* __restrict__ ea,
                        __nv_bfloat16* __restrict__ SH)
{
    const int idx = blockIdx.x * blockDim.x + threadIdx.x;
    const int row = idx >> 6;
    const int col = (idx & 63) << 2;
    const int t   = row & (LSEQ - 1);

    const int starts[8] = {0, 2047, 4093, 6138, 8182, 10225, 12267, 14308};
    float4 s = make_float4(0.f, 0.f, 0.f, 0.f);
#pragma unroll
    for (int d = 1; d <= 8; ++d) {
        if (t >= d) {
            const float wd = __ldg(&ea[starts[d - 1]]);
            uint2 u = *(const uint2*)(Hh + (size_t)(row - d) * 512 + col);
            s.x = fmaf(wd, __bfloat162float(__ushort_as_bfloat16((ushort)(u.x & 0xFFFF))), s.x);
            s.y = fmaf(wd, __bfloat162float(__ushort_as_bfloat16((ushort)(u.x >> 16))),    s.y);
            s.z = fmaf(wd, __bfloat162float(__ushort_as_bfloat16((ushort)(u.y & 0xFFFF))), s.z);
            s.w = fmaf(wd, __bfloat162float(__ushort_as_bfloat16((ushort)(u.y >> 16))),    s.w);
        }
    }
    uint2 so;
    so.x = pack_bf16(s.x, s.y);
    so.y = pack_bf16(s.z, s.w);
    *(uint2*)(SH + (size_t)row * 256 + col) = so;
}

// ---------------------------------------------------------------------------
extern "C" void kernel_launch(void* const* d_in, const int* in_sizes, int n_in,
                              void* d_out, int out_size)
{
    const float* X       = (const float*)d_in[0];
    const float* W_rel1  = (const float*)d_in[1];
    const float* b_rel1  = (const float*)d_in[2];
    const float* W_root1 = (const float*)d_in[3];
    const float* W_rel2  = (const float*)d_in[4];
    const float* b_rel2  = (const float*)d_in[5];
    const float* W_root2 = (const float*)d_in[6];
    const float* a1      = (const float*)d_in[7];
    const float* a2      = (const float*)d_in[8];
    const float* W_fc    = (const float*)d_in[9];
    const float* b_fc    = (const float*)d_in[10];
    const float* ea      = (const float*)d_in[11];
    float*       out     = (float*)d_out;

    __nv_bfloat16 *A1, *A2, *A3, *SA, *SH, *B1s, *B2s, *Bfs;
    cudaGetSymbolAddress((void**)&A1,  g_A1);
    cudaGetSymbolAddress((void**)&A2,  g_A2);
    cudaGetSymbolAddress((void**)&A3,  g_A3);
    cudaGetSymbolAddress((void**)&SA,  g_SA);
    cudaGetSymbolAddress((void**)&SH,  g_SH);
    cudaGetSymbolAddress((void**)&B1s, g_B1s);
    cudaGetSymbolAddress((void**)&B2s, g_B2s);
    cudaGetSymbolAddress((void**)&Bfs, g_Bfs);

    constexpr int SMB = NSTG * STAGEB;   // 122880
    cudaFuncSetAttribute(gemm_mma<4, true>,  cudaFuncAttributeMaxDynamicSharedMemorySize, SMB);
    cudaFuncSetAttribute(gemm_mma<3, false>, cudaFuncAttributeMaxDynamicSharedMemorySize, SMB);

    // all prep in one launch
    prep_all<<<224 + NNODE * 32 / 256, 256>>>(X, ea, W_rel1, W_root1, W_rel2, W_root2, W_fc,
                                              B1s, B2s, Bfs, A1, SA);

    // Layer 1: H1 = prelu([S.X | Xh | Xh | Xl] @ [Wrel1h|Wroot1h|Wroot1l|Wroot1h]^T + b1)
    gemm_mma<4, true><<<dim3(2, 128), 256, SMB>>>(SA, A1, A1, A1 + 128,
                                                  128, 256, 256, 256,
                                                  B1s, b_rel1, a1, A2, 128, 512);
    // S.H1
    shift_h<<<NNODE * 64 / 256, 256>>>(A2, ea, SH);

    // Layer 2
    gemm_mma<4, true><<<dim3(2, 128), 256, SMB>>>(SH, A2, A2, A2 + 256,
                                                  256, 512, 512, 512,
                                                  B2s, b_rel2, a2, A3, 256, 512);
    // FC: out = [H2h|H2h|H2l] @ [Wfch|Wfcl|Wfch]^T + b_fc
    gemm_mma<3, false><<<dim3(1, 128), 256, SMB>>>(A3, A3, A3 + 256, A3,
                                                   512, 512, 512, 512,
                                                   Bfs, b_fc, nullptr, out, 256, 128);
}

// round 11
// speedup vs baseline: 1.5085x; 1.5085x over previous
#include <cuda_runtime.h>
#include <cuda_fp16.h>
#include <cstdint>

#define NNODE 32768
#define LSEQ  2048

// ---------------- device scratch (no allocation allowed) -------------------
__device__ __align__(16) __half g_X16[NNODE * 128];   // fp16(X)
__device__ __align__(16) __half g_SA [NNODE * 128];   // fp16(S.X)
__device__ __align__(16) __half g_H1 [NNODE * 256];   // fp16(H1)
__device__ __align__(16) __half g_SH [NNODE * 256];   // fp16(S.H1)
__device__ __align__(16) __half g_H2 [NNODE * 256];   // fp16(H2)
__device__ __align__(16) __half g_B1s[256 * 384];     // [Wrel1h | Wroot1h | Wroot1l]
__device__ __align__(16) __half g_B2s[256 * 768];     // [Wrel2h | Wroot2h | Wroot2l]
__device__ __align__(16) __half g_Bfs[128 * 512];     // [Wfch | Wfcl]

// ---------------- PTX helpers ----------------------------------------------
static __device__ __forceinline__ void cp16(uint32_t dst, const void* src) {
    asm volatile("cp.async.cg.shared.global [%0], [%1], 16;" :: "r"(dst), "l"(src) : "memory");
}
static __device__ __forceinline__ void cp_commit() {
    asm volatile("cp.async.commit_group;" ::: "memory");
}

#define LDSM4(r0, r1, r2, r3, a) \
    asm volatile("ldmatrix.sync.aligned.m8n8.x4.shared.b16 {%0,%1,%2,%3}, [%4];" \
                 : "=r"(r0), "=r"(r1), "=r"(r2), "=r"(r3) : "r"(a))

#define MMA16816(d, a, b0, b1) \
    asm volatile("mma.sync.aligned.m16n8k16.row.col.f32.f16.f16.f32 " \
                 "{%0,%1,%2,%3}, {%4,%5,%6,%7}, {%8,%9}, {%0,%1,%2,%3};" \
                 : "+f"((d)[0]), "+f"((d)[1]), "+f"((d)[2]), "+f"((d)[3]) \
                 : "r"((a)[0]), "r"((a)[1]), "r"((a)[2]), "r"((a)[3]), \
                   "r"(b0), "r"(b1))

static __device__ __forceinline__ uint32_t pack_h2(float x, float y) {
    __half h0 = __float2half_rn(x), h1 = __float2half_rn(y);
    return ((uint32_t)__half_as_ushort(h1) << 16) | __half_as_ushort(h0);
}

// ---------------------------------------------------------------------------
// Segmented-K fp16 HMMA GEMM, virtual K = NSEG*KK, BK=32, 4-stage cp.async
// pipeline + register double-buffered mainloop (R7-proven schedule).
// CTA tile 256x128, 8 warps (4M x 2N), warp tile 64x64. 1 CTA/SM.
// Smem rows: 32 fp16 = 64B data at 80B stride.
// ---------------------------------------------------------------------------
#define ROWB   80
#define ATILE  (256 * ROWB)          // 20480
#define BTILE  (128 * ROWB)          // 10240
#define STAGEB (ATILE + BTILE)       // 30720
#define NSTG   4

struct Frag { uint32_t a[4][4]; uint32_t b[4][4]; };

template <int NSEG, bool LAYER>
__global__ __launch_bounds__(256, 1)
void gemm_mma(const __half* __restrict__ A0, const __half* __restrict__ A1p,
              const __half* __restrict__ A2p,
              int l0, int l1, int l2,
              const __half* __restrict__ Bs,
              const float* __restrict__ bias, const float* __restrict__ slope,
              void* __restrict__ OutP, int KK, int ldout)
{
    extern __shared__ __align__(16) char smem[];   // NSTG * STAGEB = 122880
    const uint32_t sb = (uint32_t)__cvta_generic_to_shared(smem);

    const int tid    = threadIdx.x;
    const int lane   = tid & 31;
    const int wid    = tid >> 5;
    const int warp_m = wid & 3;          // 0..3 -> 64-row block
    const int warp_n = wid >> 2;         // 0..1 -> 64-col block
    const int bm     = blockIdx.y * 256;
    const int bn     = blockIdx.x * 128;
    const int ldb    = NSEG * KK;
    const int nkk    = KK >> 5;
    const int nc     = NSEG * nkk;

    // per-thread load geometry: 4 16B units for A (256 rows), 2 for B (128 rows)
    int rA[4], qA[4];
    const __half* bsrc[2]; uint32_t adst[4], bdst[2];
#pragma unroll
    for (int i = 0; i < 4; ++i) {
        int u = i * 256 + tid, r = u >> 2, q = u & 3;
        rA[i] = r; qA[i] = q;
        adst[i] = sb + (uint32_t)(r * ROWB + q * 16);
    }
#pragma unroll
    for (int i = 0; i < 2; ++i) {
        int u = i * 256 + tid, r = u >> 2, q = u & 3;
        bsrc[i] = Bs + (size_t)(bn + r) * ldb + q * 8;
        bdst[i] = sb + ATILE + (uint32_t)(r * ROWB + q * 16);
    }

    auto issue = [&](int c) {
        if (c < nc) {
            int seg;
            if (NSEG == 3)      seg = (c >= 2 * nkk) ? 2 : (c >= nkk) ? 1 : 0;
            else                seg = (c >= nkk) ? 1 : 0;
            const __half* ab; int al;
            if      (seg == 0) { ab = A0;  al = l0; }
            else if (seg == 1) { ab = A1p; al = l1; }
            else               { ab = A2p; al = l2; }
            const __half* arow = ab + (size_t)bm * al + (c - seg * nkk) * 32;
            uint32_t st = (uint32_t)(c & (NSTG - 1)) * STAGEB;
#pragma unroll
            for (int i = 0; i < 4; ++i) cp16(adst[i] + st, arow + (size_t)rA[i] * al + qA[i] * 8);
#pragma unroll
            for (int i = 0; i < 2; ++i) cp16(bdst[i] + st, bsrc[i] + c * 32);
        }
        cp_commit();   // dummy groups keep wait_group counting valid
    };

    // ldmatrix addresses (stage/k-step invariant)
    uint32_t aAddr[4];
#pragma unroll
    for (int m = 0; m < 4; ++m) {
        int row = warp_m * 64 + m * 16 + (lane & 15);
        aAddr[m] = sb + (uint32_t)(row * ROWB + (lane >> 4) * 16);
    }
    uint32_t bAddr[4];
#pragma unroll
    for (int p = 0; p < 4; ++p) {
        int row = warp_n * 64 + (2 * p + (lane >> 4)) * 8 + (lane & 7);
        bAddr[p] = sb + ATILE + (uint32_t)(row * ROWB + ((lane >> 3) & 1) * 16);
    }

    auto ldsm_frag = [&](Frag& f, uint32_t off) {
#pragma unroll
        for (int m = 0; m < 4; ++m)
            LDSM4(f.a[m][0], f.a[m][1], f.a[m][2], f.a[m][3], aAddr[m] + off);
#pragma unroll
        for (int p = 0; p < 4; ++p)
            LDSM4(f.b[p][0], f.b[p][1], f.b[p][2], f.b[p][3], bAddr[p] + off);
    };

    float acc[4][8][4];
#pragma unroll
    for (int m = 0; m < 4; ++m)
#pragma unroll
        for (int n = 0; n < 8; ++n)
#pragma unroll
            for (int j = 0; j < 4; ++j) acc[m][n][j] = 0.0f;

    auto mma_frag = [&](const Frag& f) {
#pragma unroll
        for (int m = 0; m < 4; ++m)
#pragma unroll
            for (int n = 0; n < 8; ++n)
                MMA16816(acc[m][n], f.a[m], f.b[n >> 1][(n & 1) * 2], f.b[n >> 1][(n & 1) * 2 + 1]);
    };

    // prologue: stages 0..2 in flight, chunk 0 resident, frag0 primed
    issue(0); issue(1); issue(2);
    asm volatile("cp.async.wait_group 2;" ::: "memory");
    __syncthreads();

    Frag f0, f1;
    ldsm_frag(f0, 0);                       // chunk 0, ks 0

    for (int s = 0; s < nc; ++s) {
        const uint32_t st = (uint32_t)(s & (NSTG - 1)) * STAGEB;

        // ks0: prime ks1 frags, refill pipeline, MMA ks0
        ldsm_frag(f1, st + 32);
        issue(s + 3);
        mma_frag(f0);

        // ks1: advance smem pipeline, prime next chunk's ks0, MMA ks1
        asm volatile("cp.async.wait_group 2;" ::: "memory");   // chunk s+1 resident
        __syncthreads();                                        // all warps done reading stage s
        ldsm_frag(f0, (uint32_t)((s + 1) & (NSTG - 1)) * STAGEB);  // junk on last iter, in-bounds
        mma_frag(f1);
    }

    // ---- epilogue ----------------------------------------------------------
    if (LAYER) {
        __half* Hout = (__half*)OutP;
        const float a = __ldg(slope);
#pragma unroll
        for (int m = 0; m < 4; ++m) {
            const int r0 = bm + warp_m * 64 + m * 16 + (lane >> 2);
#pragma unroll
            for (int n = 0; n < 8; ++n) {
                const int c0 = bn + warp_n * 64 + n * 8 + (lane & 3) * 2;
                const float bx = __ldg(&bias[c0]), by = __ldg(&bias[c0 + 1]);
#pragma unroll
                for (int h = 0; h < 2; ++h) {
                    float vx = acc[m][n][h * 2 + 0] + bx;
                    float vy = acc[m][n][h * 2 + 1] + by;
                    vx = vx >= 0.f ? vx : a * vx;
                    vy = vy >= 0.f ? vy : a * vy;
                    *(uint32_t*)&Hout[(size_t)(r0 + h * 8) * ldout + c0] = pack_h2(vx, vy);
                }
            }
        }
    } else {
        float* C = (float*)OutP;
#pragma unroll
        for (int m = 0; m < 4; ++m) {
            const int r0 = bm + warp_m * 64 + m * 16 + (lane >> 2);
#pragma unroll
            for (int n = 0; n < 8; ++n) {
                const int c0 = bn + warp_n * 64 + n * 8 + (lane & 3) * 2;
                const float bx = __ldg(&bias[c0]), by = __ldg(&bias[c0 + 1]);
                *(float2*)(C + (size_t)r0 * ldout + c0) =
                    make_float2(acc[m][n][0] + bx, acc[m][n][1] + by);
                *(float2*)(C + (size_t)(r0 + 8) * ldout + c0) =
                    make_float2(acc[m][n][2] + bx, acc[m][n][3] + by);
            }
        }
    }
}

// ---------------------------------------------------------------------------
// Fused prep: weight fp16 hi(/lo) stacks + X fp16 + S.X  (one launch)
// ---------------------------------------------------------------------------
static __device__ __forceinline__ void split_unit(
    const float* __restrict__ src, __half* __restrict__ dst,
    int ldb, int offH, int offL, int K, int idx)
{
    const int per = K >> 2;
    const int row = idx / per;
    const int j   = (idx - row * per) << 2;
    float4 v = *(const float4*)(src + (size_t)row * K + j);
    __half h0 = __float2half_rn(v.x), h1 = __float2half_rn(v.y);
    __half h2 = __float2half_rn(v.z), h3 = __float2half_rn(v.w);
    uint2 hh;
    hh.x = ((uint32_t)__half_as_ushort(h1) << 16) | __half_as_ushort(h0);
    hh.y = ((uint32_t)__half_as_ushort(h3) << 16) | __half_as_ushort(h2);
    *(uint2*)(dst + (size_t)row * ldb + offH + j) = hh;
    if (offL >= 0) {
        uint2 ll;
        ll.x = pack_h2(v.x - __half2float(h0), v.y - __half2float(h1));
        ll.y = pack_h2(v.z - __half2float(h2), v.w - __half2float(h3));
        *(uint2*)(dst + (size_t)row * ldb + offL + j) = ll;
    }
}

__global__ void prep_all(const float* __restrict__ X, const float* __restrict__ ea,
                         const float* __restrict__ W_rel1, const float* __restrict__ W_root1,
                         const float* __restrict__ W_rel2, const float* __restrict__ W_root2,
                         const float* __restrict__ W_fc,
                         __half* __restrict__ B1s, __half* __restrict__ B2s,
                         __half* __restrict__ Bfs,
                         __half* __restrict__ X16, __half* __restrict__ SA)
{
    const int b   = blockIdx.x;
    const int tid = threadIdx.x;

    if (b < 224) {   // weight prep
        if (b < 32)       split_unit(W_rel1,  B1s, 384,   0,  -1, 128, b * 256 + tid);
        else if (b < 64)  split_unit(W_root1, B1s, 384, 128, 256, 128, (b - 32) * 256 + tid);
        else if (b < 128) split_unit(W_rel2,  B2s, 768,   0,  -1, 256, (b - 64) * 256 + tid);
        else if (b < 192) split_unit(W_root2, B2s, 768, 256, 512, 256, (b - 128) * 256 + tid);
        else              split_unit(W_fc,    Bfs, 512,   0, 256, 256, (b - 192) * 256 + tid);
        return;
    }

    // X prep: fp16 convert + window shift
    const int idx = (b - 224) * 256 + tid;      // 0 .. N*32
    const int row = idx >> 5;
    const int col = (idx & 31) << 2;
    const int t   = row & (LSEQ - 1);

    float4 v = *(const float4*)(X + (size_t)row * 128 + col);
    uint2 hh;
    hh.x = pack_h2(v.x, v.y);
    hh.y = pack_h2(v.z, v.w);
    *(uint2*)(X16 + (size_t)row * 128 + col) = hh;

    const int starts[8] = {0, 2047, 4093, 6138, 8182, 10225, 12267, 14308};
    float4 s = make_float4(0.f, 0.f, 0.f, 0.f);
#pragma unroll
    for (int d = 1; d <= 8; ++d) {
        if (t >= d) {
            const float wd = __ldg(&ea[starts[d - 1]]);
            float4 xd = *(const float4*)(X + (size_t)(row - d) * 128 + col);
            s.x = fmaf(wd, xd.x, s.x); s.y = fmaf(wd, xd.y, s.y);
            s.z = fmaf(wd, xd.z, s.z); s.w = fmaf(wd, xd.w, s.w);
        }
    }
    uint2 so;
    so.x = pack_h2(s.x, s.y);
    so.y = pack_h2(s.z, s.w);
    *(uint2*)(SA + (size_t)row * 128 + col) = so;
}

// ---------------------------------------------------------------------------
// shift_h: SH[i,:] = sum_d w_d * H1[i-d,:]   (H1 fp16 [N,256])
// ---------------------------------------------------------------------------
__global__ void shift_h(const __half* __restrict__ Hh, const float* __restrict__ ea,
                        __half* __restrict__ SH)
{
    const int idx = blockIdx.x * blockDim.x + threadIdx.x;
    const int row = idx >> 6;
    const int col = (idx & 63) << 2;
    const int t   = row & (LSEQ - 1);

    const int starts[8] = {0, 2047, 4093, 6138, 8182, 10225, 12267, 14308};
    float4 s = make_float4(0.f, 0.f, 0.f, 0.f);
#pragma unroll
    for (int d = 1; d <= 8; ++d) {
        if (t >= d) {
            const float wd = __ldg(&ea[starts[d - 1]]);
            uint2 u = *(const uint2*)(Hh + (size_t)(row - d) * 256 + col);
            s.x = fmaf(wd, __half2float(__ushort_as_half((ushort)(u.x & 0xFFFF))), s.x);
            s.y = fmaf(wd, __half2float(__ushort_as_half((ushort)(u.x >> 16))),    s.y);
            s.z = fmaf(wd, __half2float(__ushort_as_half((ushort)(u.y & 0xFFFF))), s.z);
            s.w = fmaf(wd, __half2float(__ushort_as_half((ushort)(u.y >> 16))),    s.w);
        }
    }
    uint2 so;
    so.x = pack_h2(s.x, s.y);
    so.y = pack_h2(s.z, s.w);
    *(uint2*)(SH + (size_t)row * 256 + col) = so;
}

// ---------------------------------------------------------------------------
extern "C" void kernel_launch(void* const* d_in, const int* in_sizes, int n_in,
                              void* d_out, int out_size)
{
    const float* X       = (const float*)d_in[0];
    const float* W_rel1  = (const float*)d_in[1];
    const float* b_rel1  = (const float*)d_in[2];
    const float* W_root1 = (const float*)d_in[3];
    const float* W_rel2  = (const float*)d_in[4];
    const float* b_rel2  = (const float*)d_in[5];
    const float* W_root2 = (const float*)d_in[6];
    const float* a1      = (const float*)d_in[7];
    const float* a2      = (const float*)d_in[8];
    const float* W_fc    = (const float*)d_in[9];
    const float* b_fc    = (const float*)d_in[10];
    const float* ea      = (const float*)d_in[11];
    float*       out     = (float*)d_out;

    __half *X16, *SA, *H1, *SH, *H2, *B1s, *B2s, *Bfs;
    cudaGetSymbolAddress((void**)&X16, g_X16);
    cudaGetSymbolAddress((void**)&SA,  g_SA);
    cudaGetSymbolAddress((void**)&H1,  g_H1);
    cudaGetSymbolAddress((void**)&SH,  g_SH);
    cudaGetSymbolAddress((void**)&H2,  g_H2);
    cudaGetSymbolAddress((void**)&B1s, g_B1s);
    cudaGetSymbolAddress((void**)&B2s, g_B2s);
    cudaGetSymbolAddress((void**)&Bfs, g_Bfs);

    constexpr int SMB = NSTG * STAGEB;   // 122880
    cudaFuncSetAttribute(gemm_mma<3, true>,  cudaFuncAttributeMaxDynamicSharedMemorySize, SMB);
    cudaFuncSetAttribute(gemm_mma<2, false>, cudaFuncAttributeMaxDynamicSharedMemorySize, SMB);

    // all prep in one launch
    prep_all<<<224 + NNODE * 32 / 256, 256>>>(X, ea, W_rel1, W_root1, W_rel2, W_root2, W_fc,
                                              B1s, B2s, Bfs, X16, SA);

    // Layer 1: H1 = prelu([S.X | X | X] @ [Wrel1h|Wroot1h|Wroot1l]^T + b1)
    gemm_mma<3, true><<<dim3(2, 128), 256, SMB>>>(SA, X16, X16,
                                                  128, 128, 128,
                                                  B1s, b_rel1, a1, H1, 128, 256);
    // S.H1
    shift_h<<<NNODE * 64 / 256, 256>>>(H1, ea, SH);

    // Layer 2: H2 = prelu([S.H1 | H1 | H1] @ [Wrel2h|Wroot2h|Wroot2l]^T + b2)
    gemm_mma<3, true><<<dim3(2, 128), 256, SMB>>>(SH, H1, H1,
                                                  256, 256, 256,
                                                  B2s, b_rel2, a2, H2, 256, 256);
    // FC: out = [H2 | H2] @ [Wfch|Wfcl]^T + b_fc
    gemm_mma<2, false><<<dim3(1, 128), 256, SMB>>>(H2, H2, H2,
                                                   256, 256, 256,
                                                   Bfs, b_fc, nullptr, out, 256, 128);
}

// round 12
// speedup vs baseline: 1.8639x; 1.2356x over previous
#include <cuda_runtime.h>
#include <cuda_fp16.h>
#include <cstdint>

#define NNODE 32768
#define LSEQ  2048

// ---------------- device scratch (no allocation allowed) -------------------
__device__ __align__(16) __half g_X16[NNODE * 128];   // fp16(X)
__device__ __align__(16) __half g_SA [NNODE * 128];   // fp16(S.X)
__device__ __align__(16) __half g_H1 [NNODE * 256];   // fp16(H1)
__device__ __align__(16) __half g_SH [NNODE * 256];   // fp16(S.H1)
__device__ __align__(16) __half g_H2 [NNODE * 256];   // fp16(H2)
__device__ __align__(16) __half g_B1s[256 * 256];     // [Wrel1h | Wroot1h]
__device__ __align__(16) __half g_B2s[256 * 512];     // [Wrel2h | Wroot2h]
__device__ __align__(16) __half g_Bfs[128 * 256];     // [Wfch]

// ---------------- PTX helpers ----------------------------------------------
static __device__ __forceinline__ void cp16(uint32_t dst, const void* src) {
    asm volatile("cp.async.cg.shared.global [%0], [%1], 16;" :: "r"(dst), "l"(src) : "memory");
}
static __device__ __forceinline__ void cp_commit() {
    asm volatile("cp.async.commit_group;" ::: "memory");
}

#define LDSM4(r0, r1, r2, r3, a) \
    asm volatile("ldmatrix.sync.aligned.m8n8.x4.shared.b16 {%0,%1,%2,%3}, [%4];" \
                 : "=r"(r0), "=r"(r1), "=r"(r2), "=r"(r3) : "r"(a))

#define MMA16816(d, a, b0, b1) \
    asm volatile("mma.sync.aligned.m16n8k16.row.col.f32.f16.f16.f32 " \
                 "{%0,%1,%2,%3}, {%4,%5,%6,%7}, {%8,%9}, {%0,%1,%2,%3};" \
                 : "+f"((d)[0]), "+f"((d)[1]), "+f"((d)[2]), "+f"((d)[3]) \
                 : "r"((a)[0]), "r"((a)[1]), "r"((a)[2]), "r"((a)[3]), \
                   "r"(b0), "r"(b1))

static __device__ __forceinline__ uint32_t pack_h2(float x, float y) {
    __half h0 = __float2half_rn(x), h1 = __float2half_rn(y);
    return ((uint32_t)__half_as_ushort(h1) << 16) | __half_as_ushort(h0);
}

// ---------------------------------------------------------------------------
// Segmented-K fp16 HMMA GEMM, virtual K = NSEG*KK, BK=32, 4-stage cp.async
// pipeline + register double-buffered mainloop (R7-proven schedule).
// CTA tile 256x128, 8 warps (4M x 2N), warp tile 64x64. 1 CTA/SM.
// Smem rows: 32 fp16 = 64B data at 80B stride.
// ---------------------------------------------------------------------------
#define ROWB   80
#define ATILE  (256 * ROWB)          // 20480
#define BTILE  (128 * ROWB)          // 10240
#define STAGEB (ATILE + BTILE)       // 30720
#define NSTG   4

struct Frag { uint32_t a[4][4]; uint32_t b[4][4]; };

template <int NSEG, bool LAYER>
__global__ __launch_bounds__(256, 1)
void gemm_mma(const __half* __restrict__ A0, const __half* __restrict__ A1p,
              int l0, int l1,
              const __half* __restrict__ Bs,
              const float* __restrict__ bias, const float* __restrict__ slope,
              void* __restrict__ OutP, int KK, int ldout)
{
    extern __shared__ __align__(16) char smem[];   // NSTG * STAGEB = 122880
    const uint32_t sb = (uint32_t)__cvta_generic_to_shared(smem);

    const int tid    = threadIdx.x;
    const int lane   = tid & 31;
    const int wid    = tid >> 5;
    const int warp_m = wid & 3;          // 0..3 -> 64-row block
    const int warp_n = wid >> 2;         // 0..1 -> 64-col block
    const int bm     = blockIdx.y * 256;
    const int bn     = blockIdx.x * 128;
    const int ldb    = NSEG * KK;
    const int nkk    = KK >> 5;
    const int nc     = NSEG * nkk;

    // per-thread load geometry: 4 16B units for A (256 rows), 2 for B (128 rows)
    int rA[4], qA[4];
    const __half* bsrc[2]; uint32_t adst[4], bdst[2];
#pragma unroll
    for (int i = 0; i < 4; ++i) {
        int u = i * 256 + tid, r = u >> 2, q = u & 3;
        rA[i] = r; qA[i] = q;
        adst[i] = sb + (uint32_t)(r * ROWB + q * 16);
    }
#pragma unroll
    for (int i = 0; i < 2; ++i) {
        int u = i * 256 + tid, r = u >> 2, q = u & 3;
        bsrc[i] = Bs + (size_t)(bn + r) * ldb + q * 8;
        bdst[i] = sb + ATILE + (uint32_t)(r * ROWB + q * 16);
    }

    auto issue = [&](int c) {
        if (c < nc) {
            int seg = (NSEG == 2) ? (c >= nkk ? 1 : 0) : 0;
            const __half* ab; int al;
            if (seg == 0) { ab = A0;  al = l0; }
            else          { ab = A1p; al = l1; }
            const __half* arow = ab + (size_t)bm * al + (c - seg * nkk) * 32;
            uint32_t st = (uint32_t)(c & (NSTG - 1)) * STAGEB;
#pragma unroll
            for (int i = 0; i < 4; ++i) cp16(adst[i] + st, arow + (size_t)rA[i] * al + qA[i] * 8);
#pragma unroll
            for (int i = 0; i < 2; ++i) cp16(bdst[i] + st, bsrc[i] + c * 32);
        }
        cp_commit();   // dummy groups keep wait_group counting valid
    };

    // ldmatrix addresses (stage/k-step invariant)
    uint32_t aAddr[4];
#pragma unroll
    for (int m = 0; m < 4; ++m) {
        int row = warp_m * 64 + m * 16 + (lane & 15);
        aAddr[m] = sb + (uint32_t)(row * ROWB + (lane >> 4) * 16);
    }
    uint32_t bAddr[4];
#pragma unroll
    for (int p = 0; p < 4; ++p) {
        int row = warp_n * 64 + (2 * p + (lane >> 4)) * 8 + (lane & 7);
        bAddr[p] = sb + ATILE + (uint32_t)(row * ROWB + ((lane >> 3) & 1) * 16);
    }

    auto ldsm_frag = [&](Frag& f, uint32_t off) {
#pragma unroll
        for (int m = 0; m < 4; ++m)
            LDSM4(f.a[m][0], f.a[m][1], f.a[m][2], f.a[m][3], aAddr[m] + off);
#pragma unroll
        for (int p = 0; p < 4; ++p)
            LDSM4(f.b[p][0], f.b[p][1], f.b[p][2], f.b[p][3], bAddr[p] + off);
    };

    float acc[4][8][4];
#pragma unroll
    for (int m = 0; m < 4; ++m)
#pragma unroll
        for (int n = 0; n < 8; ++n)
#pragma unroll
            for (int j = 0; j < 4; ++j) acc[m][n][j] = 0.0f;

    auto mma_frag = [&](const Frag& f) {
#pragma unroll
        for (int m = 0; m < 4; ++m)
#pragma unroll
            for (int n = 0; n < 8; ++n)
                MMA16816(acc[m][n], f.a[m], f.b[n >> 1][(n & 1) * 2], f.b[n >> 1][(n & 1) * 2 + 1]);
    };

    // prologue: stages 0..2 in flight, chunk 0 resident, frag0 primed
    issue(0); issue(1); issue(2);
    asm volatile("cp.async.wait_group 2;" ::: "memory");
    __syncthreads();

    Frag f0, f1;
    ldsm_frag(f0, 0);                       // chunk 0, ks 0

    for (int s = 0; s < nc; ++s) {
        const uint32_t st = (uint32_t)(s & (NSTG - 1)) * STAGEB;

        // ks0: prime ks1 frags, refill pipeline, MMA ks0
        ldsm_frag(f1, st + 32);
        issue(s + 3);
        mma_frag(f0);

        // ks1: advance smem pipeline, prime next chunk's ks0, MMA ks1
        asm volatile("cp.async.wait_group 2;" ::: "memory");   // chunk s+1 resident
        __syncthreads();                                        // all warps done reading stage s
        ldsm_frag(f0, (uint32_t)((s + 1) & (NSTG - 1)) * STAGEB);  // junk on last iter, in-bounds
        mma_frag(f1);
    }

    // ---- epilogue ----------------------------------------------------------
    if (LAYER) {
        __half* Hout = (__half*)OutP;
        const float a = __ldg(slope);
#pragma unroll
        for (int m = 0; m < 4; ++m) {
            const int r0 = bm + warp_m * 64 + m * 16 + (lane >> 2);
#pragma unroll
            for (int n = 0; n < 8; ++n) {
                const int c0 = bn + warp_n * 64 + n * 8 + (lane & 3) * 2;
                const float bx = __ldg(&bias[c0]), by = __ldg(&bias[c0 + 1]);
#pragma unroll
                for (int h = 0; h < 2; ++h) {
                    float vx = acc[m][n][h * 2 + 0] + bx;
                    float vy = acc[m][n][h * 2 + 1] + by;
                    vx = vx >= 0.f ? vx : a * vx;
                    vy = vy >= 0.f ? vy : a * vy;
                    *(uint32_t*)&Hout[(size_t)(r0 + h * 8) * ldout + c0] = pack_h2(vx, vy);
                }
            }
        }
    } else {
        float* C = (float*)OutP;
#pragma unroll
        for (int m = 0; m < 4; ++m) {
            const int r0 = bm + warp_m * 64 + m * 16 + (lane >> 2);
#pragma unroll
            for (int n = 0; n < 8; ++n) {
                const int c0 = bn + warp_n * 64 + n * 8 + (lane & 3) * 2;
                const float bx = __ldg(&bias[c0]), by = __ldg(&bias[c0 + 1]);
                *(float2*)(C + (size_t)r0 * ldout + c0) =
                    make_float2(acc[m][n][0] + bx, acc[m][n][1] + by);
                *(float2*)(C + (size_t)(r0 + 8) * ldout + c0) =
                    make_float2(acc[m][n][2] + bx, acc[m][n][3] + by);
            }
        }
    }
}

// ---------------------------------------------------------------------------
// Fused prep: weight fp16 stacks + X fp16 + S.X  (one launch)
// ---------------------------------------------------------------------------
static __device__ __forceinline__ void conv_unit(
    const float* __restrict__ src, __half* __restrict__ dst,
    int ldb, int offH, int K, int idx)
{
    const int per = K >> 2;
    const int row = idx / per;
    const int j   = (idx - row * per) << 2;
    float4 v = *(const float4*)(src + (size_t)row * K + j);
    uint2 hh;
    hh.x = pack_h2(v.x, v.y);
    hh.y = pack_h2(v.z, v.w);
    *(uint2*)(dst + (size_t)row * ldb + offH + j) = hh;
}

__global__ void prep_all(const float* __restrict__ X, const float* __restrict__ ea,
                         const float* __restrict__ W_rel1, const float* __restrict__ W_root1,
                         const float* __restrict__ W_rel2, const float* __restrict__ W_root2,
                         const float* __restrict__ W_fc,
                         __half* __restrict__ B1s, __half* __restrict__ B2s,
                         __half* __restrict__ Bfs,
                         __half* __restrict__ X16, __half* __restrict__ SA)
{
    const int b   = blockIdx.x;
    const int tid = threadIdx.x;

    if (b < 224) {   // weight prep
        if (b < 32)       conv_unit(W_rel1,  B1s, 256,   0, 128, b * 256 + tid);
        else if (b < 64)  conv_unit(W_root1, B1s, 256, 128, 128, (b - 32) * 256 + tid);
        else if (b < 128) conv_unit(W_rel2,  B2s, 512,   0, 256, (b - 64) * 256 + tid);
        else if (b < 192) conv_unit(W_root2, B2s, 512, 256, 256, (b - 128) * 256 + tid);
        else              conv_unit(W_fc,    Bfs, 256,   0, 256, (b - 192) * 256 + tid);
        return;
    }

    // X prep: fp16 convert + window shift
    const int idx = (b - 224) * 256 + tid;      // 0 .. N*32
    const int row = idx >> 5;
    const int col = (idx & 31) << 2;
    const int t   = row & (LSEQ - 1);

    float4 v = *(const float4*)(X + (size_t)row * 128 + col);
    uint2 hh;
    hh.x = pack_h2(v.x, v.y);
    hh.y = pack_h2(v.z, v.w);
    *(uint2*)(X16 + (size_t)row * 128 + col) = hh;

    const int starts[8] = {0, 2047, 4093, 6138, 8182, 10225, 12267, 14308};
    float4 s = make_float4(0.f, 0.f, 0.f, 0.f);
#pragma unroll
    for (int d = 1; d <= 8; ++d) {
        if (t >= d) {
            const float wd = __ldg(&ea[starts[d - 1]]);
            float4 xd = *(const float4*)(X + (size_t)(row - d) * 128 + col);
            s.x = fmaf(wd, xd.x, s.x); s.y = fmaf(wd, xd.y, s.y);
            s.z = fmaf(wd, xd.z, s.z); s.w = fmaf(wd, xd.w, s.w);
        }
    }
    uint2 so;
    so.x = pack_h2(s.x, s.y);
    so.y = pack_h2(s.z, s.w);
    *(uint2*)(SA + (size_t)row * 128 + col) = so;
}

// ---------------------------------------------------------------------------
// shift_h: SH[i,:] = sum_d w_d * H1[i-d,:]   (H1 fp16 [N,256])
// ---------------------------------------------------------------------------
__global__ void shift_h(const __half* __restrict__ Hh, const float* __restrict__ ea,
                        __half* __restrict__ SH)
{
    const int idx = blockIdx.x * blockDim.x + threadIdx.x;
    const int row = idx >> 6;
    const int col = (idx & 63) << 2;
    const int t   = row & (LSEQ - 1);

    const int starts[8] = {0, 2047, 4093, 6138, 8182, 10225, 12267, 14308};
    float4 s = make_float4(0.f, 0.f, 0.f, 0.f);
#pragma unroll
    for (int d = 1; d <= 8; ++d) {
        if (t >= d) {
            const float wd = __ldg(&ea[starts[d - 1]]);
            uint2 u = *(const uint2*)(Hh + (size_t)(row - d) * 256 + col);
            s.x = fmaf(wd, __half2float(__ushort_as_half((ushort)(u.x & 0xFFFF))), s.x);
            s.y = fmaf(wd, __half2float(__ushort_as_half((ushort)(u.x >> 16))),    s.y);
            s.z = fmaf(wd, __half2float(__ushort_as_half((ushort)(u.y & 0xFFFF))), s.z);
            s.w = fmaf(wd, __half2float(__ushort_as_half((ushort)(u.y >> 16))),    s.w);
        }
    }
    uint2 so;
    so.x = pack_h2(s.x, s.y);
    so.y = pack_h2(s.z, s.w);
    *(uint2*)(SH + (size_t)row * 256 + col) = so;
}

// ---------------------------------------------------------------------------
extern "C" void kernel_launch(void* const* d_in, const int* in_sizes, int n_in,
                              void* d_out, int out_size)
{
    const float* X       = (const float*)d_in[0];
    const float* W_rel1  = (const float*)d_in[1];
    const float* b_rel1  = (const float*)d_in[2];
    const float* W_root1 = (const float*)d_in[3];
    const float* W_rel2  = (const float*)d_in[4];
    const float* b_rel2  = (const float*)d_in[5];
    const float* W_root2 = (const float*)d_in[6];
    const float* a1      = (const float*)d_in[7];
    const float* a2      = (const float*)d_in[8];
    const float* W_fc    = (const float*)d_in[9];
    const float* b_fc    = (const float*)d_in[10];
    const float* ea      = (const float*)d_in[11];
    float*       out     = (float*)d_out;

    __half *X16, *SA, *H1, *SH, *H2, *B1s, *B2s, *Bfs;
    cudaGetSymbolAddress((void**)&X16, g_X16);
    cudaGetSymbolAddress((void**)&SA,  g_SA);
    cudaGetSymbolAddress((void**)&H1,  g_H1);
    cudaGetSymbolAddress((void**)&SH,  g_SH);
    cudaGetSymbolAddress((void**)&H2,  g_H2);
    cudaGetSymbolAddress((void**)&B1s, g_B1s);
    cudaGetSymbolAddress((void**)&B2s, g_B2s);
    cudaGetSymbolAddress((void**)&Bfs, g_Bfs);

    constexpr int SMB = NSTG * STAGEB;   // 122880
    cudaFuncSetAttribute(gemm_mma<2, true>,  cudaFuncAttributeMaxDynamicSharedMemorySize, SMB);
    cudaFuncSetAttribute(gemm_mma<1, false>, cudaFuncAttributeMaxDynamicSharedMemorySize, SMB);

    // all prep in one launch
    prep_all<<<224 + NNODE * 32 / 256, 256>>>(X, ea, W_rel1, W_root1, W_rel2, W_root2, W_fc,
                                              B1s, B2s, Bfs, X16, SA);

    // Layer 1: H1 = prelu([S.X | X] @ [Wrel1h|Wroot1h]^T + b1)
    gemm_mma<2, true><<<dim3(2, 128), 256, SMB>>>(SA, X16,
                                                  128, 128,
                                                  B1s, b_rel1, a1, H1, 128, 256);
    // S.H1
    shift_h<<<NNODE * 64 / 256, 256>>>(H1, ea, SH);

    // Layer 2: H2 = prelu([S.H1 | H1] @ [Wrel2h|Wroot2h]^T + b2)
    gemm_mma<2, true><<<dim3(2, 128), 256, SMB>>>(SH, H1,
                                                  256, 256,
                                                  B2s, b_rel2, a2, H2, 256, 256);
    // FC: out = H2 @ Wfch^T + b_fc
    gemm_mma<1, false><<<dim3(1, 128), 256, SMB>>>(H2, H2,
                                                   256, 256,
                                                   Bfs, b_fc, nullptr, out, 256, 128);
}